// round 1
// baseline (speedup 1.0000x reference)
#include <cuda_runtime.h>

#define NW   10
#define QDIM 1024
#define NBLK 4
#define NTHREADS 512

// Precomputed phase tables (params-only, batch-independent).
// A[k][s] = exp(-i/2 * p0.z[s])
// B[k][s] = exp(-i/2 * (p3.z[s] + p2.z[perm[s]]))   (applied with gather by perm)
// C[k][s] = exp(-i/2 * p5.z[perm[s]])               (applied with gather by perm)
__device__ float2 gA[NBLK][QDIM];
__device__ float2 gB[NBLK][QDIM];
__device__ float2 gC[NBLK][QDIM];
__device__ float2 gRy[NBLK][2][NW];   // (cos(th/2), sin(th/2))

// CX-ring permutation: pairs (0,1)...(8,9),(9,0) applied as P = P[g] forward,
// so perm(s) = g1(g2(...g10(s))) -> apply pairs in REVERSE order.
__device__ __forceinline__ int perm_of(int s) {
    { int bit = s & 1; s ^= bit << 9; }           // pair (c=9, t=0)
    #pragma unroll
    for (int c = 8; c >= 0; --c) {                // pairs (c, c+1), c = 8..0
        int bit = (s >> (9 - c)) & 1;
        s ^= bit << (8 - c);                      // 9 - (c+1)
    }
    return s;
}

__device__ __forceinline__ float dotz(const float* __restrict__ p, int s) {
    float d = 0.f;
    #pragma unroll
    for (int w = 0; w < NW; ++w)
        d += ((s >> (9 - w)) & 1) ? -p[w] : p[w];
    return d;
}

__global__ void precompute_kernel(const float* __restrict__ params) {
    int s = threadIdx.x;                          // 0..1023
    if (s < NBLK * 2 * NW) {                      // RY coefficient table
        int k = s / (2 * NW), r = s % (2 * NW);
        int sweep = r / NW, w = r % NW;
        float th = params[(k * 6 + (sweep ? 4 : 1)) * NW + w];
        gRy[k][sweep][w] = make_float2(cosf(0.5f * th), sinf(0.5f * th));
    }
    int ps = perm_of(s);
    #pragma unroll
    for (int k = 0; k < NBLK; ++k) {
        const float* p = params + k * 6 * NW;
        float aA = dotz(p + 0 * NW, s);
        float aB = dotz(p + 3 * NW, s) + dotz(p + 2 * NW, ps);
        float aC = dotz(p + 5 * NW, ps);
        float c, si;
        sincosf(-0.5f * aA, &si, &c); gA[k][s] = make_float2(c, si);
        sincosf(-0.5f * aB, &si, &c); gB[k][s] = make_float2(c, si);
        sincosf(-0.5f * aC, &si, &c); gC[k][s] = make_float2(c, si);
    }
}

__device__ __forceinline__ float2 cmul(float2 a, float2 b) {
    return make_float2(a.x * b.x - a.y * b.y, a.x * b.y + a.y * b.x);
}
// RY 2x2: new0 = c*u - s*v ; new1 = s*u + c*v   (real rotation on complex pair)
__device__ __forceinline__ void rotp(float2& u, float2& v, float c, float s) {
    float2 nu = make_float2(fmaf(c, u.x, -s * v.x), fmaf(c, u.y, -s * v.y));
    float2 nv = make_float2(fmaf(s, u.x,  c * v.x), fmaf(s, u.y,  c * v.y));
    u = nu; v = nv;
}

__global__ __launch_bounds__(NTHREADS)
void qsim_kernel(const float* __restrict__ x, float* __restrict__ out) {
    __shared__ float2 sh[QDIM];
    __shared__ float  sx[NW];
    __shared__ float  sred[NTHREADS / 32][NW];

    const int b = blockIdx.x;
    const int t = threadIdx.x;
    if (t < NW) sx[t] = x[b * NW + t];

    const int s0 = 2 * t, s1 = 2 * t + 1;
    const int p0 = perm_of(s0), p1 = perm_of(s1);

    // |0...0> initial state, held in registers (own amplitudes)
    float2 a0 = make_float2(t == 0 ? 1.f : 0.f, 0.f);
    float2 a1 = make_float2(0.f, 0.f);

    for (int k = 0; k < NBLK; ++k) {
        // --- diag A fused with RY sweep1, wire 9 (bit 0 = in-register pair) ---
        {
            float4 Av = *reinterpret_cast<const float4*>(&gA[k][s0]);
            a0 = cmul(a0, make_float2(Av.x, Av.y));
            a1 = cmul(a1, make_float2(Av.z, Av.w));
            float2 rc = gRy[k][0][9];
            rotp(a0, a1, rc.x, rc.y);
            sh[s0] = a0; sh[s1] = a1;
        }
        // --- RY sweep1, wires 8..0 (bit positions 1..9) ---
        #pragma unroll
        for (int bp = 1; bp <= 9; ++bp) {
            __syncthreads();
            int m  = 1 << bp;
            int i0 = ((t >> bp) << (bp + 1)) | (t & (m - 1));
            int i1 = i0 | m;
            float2 u = sh[i0], v = sh[i1];
            float2 rc = gRy[k][0][9 - bp];
            rotp(u, v, rc.x, rc.y);
            sh[i0] = u; sh[i1] = v;
        }
        __syncthreads();
        // --- gather-perm + combined rz(p2)/rz(p3), fused with sweep2 wire 9 ---
        {
            float4 Bv = *reinterpret_cast<const float4*>(&gB[k][s0]);
            a0 = cmul(sh[p0], make_float2(Bv.x, Bv.y));
            a1 = cmul(sh[p1], make_float2(Bv.z, Bv.w));
            float2 rc = gRy[k][1][9];
            rotp(a0, a1, rc.x, rc.y);
        }
        __syncthreads();                 // all gathers read before overwrite
        sh[s0] = a0; sh[s1] = a1;
        // --- RY sweep2, wires 8..0 ---
        #pragma unroll
        for (int bp = 1; bp <= 9; ++bp) {
            __syncthreads();
            int m  = 1 << bp;
            int i0 = ((t >> bp) << (bp + 1)) | (t & (m - 1));
            int i1 = i0 | m;
            float2 u = sh[i0], v = sh[i1];
            float2 rc = gRy[k][1][9 - bp];
            rotp(u, v, rc.x, rc.y);
            sh[i0] = u; sh[i1] = v;
        }
        __syncthreads();
        // --- gather-perm + rz(p5), then batch encoding phase (k < last) ---
        {
            float4 Cv = *reinterpret_cast<const float4*>(&gC[k][s0]);
            a0 = cmul(sh[p0], make_float2(Cv.x, Cv.y));
            a1 = cmul(sh[p1], make_float2(Cv.z, Cv.w));
        }
        if (k < NBLK - 1) {
            float ang0 = 0.f, ang1 = 0.f;
            #pragma unroll
            for (int w = 0; w < NW; ++w) {
                float xv = sx[w];
                ang0 += ((s0 >> (9 - w)) & 1) ? -xv : xv;
                ang1 += ((s1 >> (9 - w)) & 1) ? -xv : xv;
            }
            float c0, si0, c1, si1;
            sincosf(-0.5f * ang0, &si0, &c0);
            sincosf(-0.5f * ang1, &si1, &c1);
            a0 = cmul(a0, make_float2(c0, si0));
            a1 = cmul(a1, make_float2(c1, si1));
            __syncthreads();             // gathers done before next block's stores
        }
    }

    // --- probs -> expectation values out[b][w] = sum_s probs[s] * zval[w][s] ---
    float P0 = a0.x * a0.x + a0.y * a0.y;
    float P1 = a1.x * a1.x + a1.y * a1.y;
    float acc[NW];
    #pragma unroll
    for (int w = 0; w < NW; ++w) {
        if (w == 9) acc[w] = P0 - P1;                       // bit0 differs in pair
        else        acc[w] = ((s0 >> (9 - w)) & 1) ? -(P0 + P1) : (P0 + P1);
    }
    #pragma unroll
    for (int off = 16; off > 0; off >>= 1) {
        #pragma unroll
        for (int w = 0; w < NW; ++w)
            acc[w] += __shfl_down_sync(0xffffffffu, acc[w], off);
    }
    int warp = t >> 5, lane = t & 31;
    if (lane == 0) {
        #pragma unroll
        for (int w = 0; w < NW; ++w) sred[warp][w] = acc[w];
    }
    __syncthreads();
    if (t < NW) {
        float ssum = 0.f;
        #pragma unroll
        for (int j = 0; j < NTHREADS / 32; ++j) ssum += sred[j][t];
        out[b * NW + t] = ssum;
    }
}

extern "C" void kernel_launch(void* const* d_in, const int* in_sizes, int n_in,
                              void* d_out, int out_size) {
    const float* x      = (const float*)d_in[0];
    const float* params = (const float*)d_in[1];
    float* out = (float*)d_out;
    int bsz = in_sizes[0] / NW;           // 2048
    precompute_kernel<<<1, QDIM>>>(params);
    qsim_kernel<<<bsz, NTHREADS>>>(x, out);
}

// round 2
// speedup vs baseline: 2.2353x; 2.2353x over previous
#include <cuda_runtime.h>

#define NW   10
#define QDIM 1024
#define NBLK 4
#define WPB  4                    // warps (batch elements) per CTA
#define NTHREADS (WPB * 32)

// Precomputed phase tables (params-only, batch-independent).
// A[k][s] = exp(-i/2 * p0.z[s])
// B[k][s] = exp(-i/2 * (p3.z[s] + p2.z[perm[s]]))   (applied with gather by perm)
// C[k][s] = exp(-i/2 * p5.z[perm[s]])               (applied with gather by perm)
__device__ float2 gA[NBLK][QDIM];
__device__ float2 gB[NBLK][QDIM];
__device__ float2 gC[NBLK][QDIM];
__device__ float2 gRy[NBLK][2][NW];   // (cos(th/2), sin(th/2))

// CX-ring permutation, closed form (GF(2)-linear):
// out_i = b_i ^ b_{i+1} (i=0..7), out8 = b8^b9^b0, out9 = b9^b0
__host__ __device__ __forceinline__ int perm_of(int s) {
    int lo = (s ^ (s >> 1)) & 0xFF;
    int b0 = s & 1, b8 = (s >> 8) & 1, b9 = (s >> 9) & 1;
    return lo | ((b8 ^ b9 ^ b0) << 8) | ((b9 ^ b0) << 9);
}

__device__ __forceinline__ float dotz(const float* __restrict__ p, int s) {
    float d = 0.f;
    #pragma unroll
    for (int w = 0; w < NW; ++w)
        d += ((s >> (9 - w)) & 1) ? -p[w] : p[w];
    return d;
}

__global__ void precompute_kernel(const float* __restrict__ params) {
    int s = threadIdx.x;                          // 0..1023
    if (s < NBLK * 2 * NW) {                      // RY coefficient table
        int k = s / (2 * NW), r = s % (2 * NW);
        int sweep = r / NW, w = r % NW;
        float th = params[(k * 6 + (sweep ? 4 : 1)) * NW + w];
        gRy[k][sweep][w] = make_float2(cosf(0.5f * th), sinf(0.5f * th));
    }
    int ps = perm_of(s);
    #pragma unroll
    for (int k = 0; k < NBLK; ++k) {
        const float* p = params + k * 6 * NW;
        float aA = dotz(p + 0 * NW, s);
        float aB = dotz(p + 3 * NW, s) + dotz(p + 2 * NW, ps);
        float aC = dotz(p + 5 * NW, ps);
        float c, si;
        sincosf(-0.5f * aA, &si, &c); gA[k][s] = make_float2(c, si);
        sincosf(-0.5f * aB, &si, &c); gB[k][s] = make_float2(c, si);
        sincosf(-0.5f * aC, &si, &c); gC[k][s] = make_float2(c, si);
    }
}

__device__ __forceinline__ float2 cmul(float2 a, float2 b) {
    return make_float2(a.x * b.x - a.y * b.y, a.x * b.y + a.y * b.x);
}
// RY 2x2 on a register pair: u' = c*u - s*v ; v' = s*u + c*v
__device__ __forceinline__ void rotp(float2& u, float2& v, float c, float s) {
    float2 nu = make_float2(fmaf(c, u.x, -s * v.x), fmaf(c, u.y, -s * v.y));
    float2 nv = make_float2(fmaf(s, u.x,  c * v.x), fmaf(s, u.y,  c * v.y));
    u = nu; v = nv;
}

// Layouts:
//   L0: amplitude s = (h<<5)|lane   (reg h = bits 9..5, lane = bits 4..0)
//   L1: amplitude s = (lane<<5)|h   (lane = bits 9..5, reg h = bits 4..0)
// Shared swizzle: phys(s) = s ^ ((s>>5)&31)  -> conflict-free for all 4 patterns.
__global__ __launch_bounds__(NTHREADS)
void qsim_kernel(const float* __restrict__ x, float* __restrict__ out) {
    __shared__ float2 stage[WPB][QDIM];

    const int lane = threadIdx.x & 31;
    const int wid  = threadIdx.x >> 5;
    const int b    = blockIdx.x * WPB + wid;
    float2* st = stage[wid];

    float xv[NW];
    #pragma unroll
    for (int w = 0; w < NW; ++w) xv[w] = __ldg(&x[b * NW + w]);

    // Per-thread gather constant: addr = D[h] ^ pladj
    const int pl    = perm_of(lane);
    const int pladj = pl ^ ((lane & 1) ? 0x18 : 0);

    // Encoding angle contribution from lane bits (wires 5..9, bit 9-w = lane bit)
    float langle = 0.f;
    #pragma unroll
    for (int w = 5; w < NW; ++w)
        langle += ((lane >> (9 - w)) & 1) ? -xv[w] : xv[w];

    // |0...0>  (s=0 -> lane 0, reg 0)
    float2 r[32];
    #pragma unroll
    for (int h = 0; h < 32; ++h) r[h] = make_float2(0.f, 0.f);
    if (lane == 0) r[0].x = 1.f;

    for (int k = 0; k < NBLK; ++k) {
        // --- diag A (L0): s = (h<<5)|lane ---
        #pragma unroll
        for (int h = 0; h < 32; ++h)
            r[h] = cmul(r[h], __ldg(&gA[k][(h << 5) | lane]));

        #pragma unroll
        for (int sweep = 0; sweep < 2; ++sweep) {
            // L0 in-register wires: w = 0..4, reg-bit rb = 4-w
            #pragma unroll
            for (int rb = 0; rb < 5; ++rb) {
                float2 rc = gRy[k][sweep][4 - rb];
                #pragma unroll
                for (int h = 0; h < 32; ++h)
                    if (!(h & (1 << rb)))
                        rotp(r[h], r[h | (1 << rb)], rc.x, rc.y);
            }
            // transpose L0 -> L1 through private warp stage
            __syncwarp();
            #pragma unroll
            for (int h = 0; h < 32; ++h)
                st[(h << 5) | (lane ^ h)] = r[h];
            __syncwarp();
            #pragma unroll
            for (int h = 0; h < 32; ++h)
                r[h] = st[(lane << 5) | (h ^ lane)];
            // L1 in-register wires: w = 5..9, reg-bit rb = 9-w
            #pragma unroll
            for (int rb = 0; rb < 5; ++rb) {
                float2 rc = gRy[k][sweep][9 - rb];
                #pragma unroll
                for (int h = 0; h < 32; ++h)
                    if (!(h & (1 << rb)))
                        rotp(r[h], r[h | (1 << rb)], rc.x, rc.y);
            }
            // write (L1) -> gather by perm into L0, fused diag B (sweep0) / C (sweep1)
            __syncwarp();
            #pragma unroll
            for (int h = 0; h < 32; ++h)
                st[(lane << 5) | (h ^ lane)] = r[h];
            __syncwarp();
            const float2* __restrict__ T = (sweep == 0) ? gB[k] : gC[k];
            #pragma unroll
            for (int h = 0; h < 32; ++h) {
                const int C = perm_of(h << 5);            // compile-time
                const int D = C ^ ((C >> 5) & 31);        // compile-time
                float2 v  = st[D ^ pladj];
                r[h] = cmul(v, __ldg(&T[(h << 5) | lane]));
            }
        }

        // --- batch encoding phase (k < last), state in L0 ---
        if (k != NBLK - 1) {
            #pragma unroll
            for (int h = 0; h < 32; ++h) {
                float ang = langle;
                #pragma unroll
                for (int w = 0; w < 5; ++w)
                    ang += ((h >> (4 - w)) & 1) ? -xv[w] : xv[w];
                float c, si;
                __sincosf(-0.5f * ang, &si, &c);
                r[h] = cmul(r[h], make_float2(c, si));
            }
        }
    }

    // --- expectation values: out[b][w] = sum_s |a_s|^2 * z[w][s] ---
    float acc[NW];
    #pragma unroll
    for (int w = 0; w < NW; ++w) acc[w] = 0.f;
    float totP = 0.f;
    #pragma unroll
    for (int h = 0; h < 32; ++h) {
        float p = r[h].x * r[h].x + r[h].y * r[h].y;
        totP += p;
        #pragma unroll
        for (int w = 0; w < 5; ++w)                     // wires 0..4 <- reg bits
            acc[w] += ((h >> (4 - w)) & 1) ? -p : p;
    }
    #pragma unroll
    for (int w = 5; w < NW; ++w)                        // wires 5..9 <- lane bits
        acc[w] = ((lane >> (9 - w)) & 1) ? -totP : totP;

    #pragma unroll
    for (int off = 16; off; off >>= 1)
        #pragma unroll
        for (int w = 0; w < NW; ++w)
            acc[w] += __shfl_xor_sync(0xffffffffu, acc[w], off);

    if (lane == 0) {
        #pragma unroll
        for (int w = 0; w < NW; ++w) out[b * NW + w] = acc[w];
    }
}

extern "C" void kernel_launch(void* const* d_in, const int* in_sizes, int n_in,
                              void* d_out, int out_size) {
    const float* x      = (const float*)d_in[0];
    const float* params = (const float*)d_in[1];
    float* out = (float*)d_out;
    int bsz = in_sizes[0] / NW;           // 2048
    precompute_kernel<<<1, QDIM>>>(params);
    qsim_kernel<<<bsz / WPB, NTHREADS>>>(x, out);
}